// round 7
// baseline (speedup 1.0000x reference)
#include <cuda_runtime.h>
#include <math.h>

#define BB 2
#define NN 4096
#define KK 30

#define SZ_POS (BB*NN*KK*16)
#define SZ_AD  (BB*NN*3)
#define SZ_OF  (BB*NN*KK*3)
#define SZ_GS  (BB*NN*KK*15)
#define SZ_DN  (BB*NN*KK)

#define OFF_POS 0
#define OFF_AD  (OFF_POS + SZ_POS)
#define OFF_OF  (OFF_AD  + SZ_AD)
#define OFF_GS  (OFF_OF  + SZ_OF)
#define OFF_DN  (OFF_GS  + SZ_GS)
#define OFF_EI  (OFF_DN  + SZ_DN)

// ---- scratch (no allocations allowed) ----
static __device__ int   g_eidx[BB*NN*KK];
static __device__ float g_Omat[BB*NN*9];
static __device__ float g_freq[8];
static __device__ float g_mu[15];

// ---- exact-rounding helpers ----
__device__ __forceinline__ float fadd_(float a, float b){ return __fadd_rn(a,b); }
__device__ __forceinline__ float fsub_(float a, float b){ return __fsub_rn(a,b); }
__device__ __forceinline__ float fmul_(float a, float b){ return __fmul_rn(a,b); }
__device__ __forceinline__ float dot3_(float ax,float ay,float az,
                                       float bx,float by,float bz){
    return fadd_(fadd_(fmul_(ax,bx), fmul_(ay,by)), fmul_(az,bz));
}
__device__ __forceinline__ void norm3_(float &x, float &y, float &z){
    float n = __fsqrt_rn(dot3_(x,y,z,x,y,z));
    n = fmaxf(n, 1e-12f);
    x = __fdiv_rn(x,n); y = __fdiv_rn(y,n); z = __fdiv_rn(z,n);
}
__device__ __forceinline__ void cross3_(float ax,float ay,float az,
                                        float bx,float by,float bz,
                                        float &cx,float &cy,float &cz){
    cx = fsub_(fmul_(ay,bz), fmul_(az,by));
    cy = fsub_(fmul_(az,bx), fmul_(ax,bz));
    cz = fsub_(fmul_(ax,by), fmul_(ay,bx));
}
__device__ __forceinline__ float d2_exact(float xi,float yi,float zi,
                                          float xj,float yj,float zj){
    float dx = fsub_(xj,xi), dy = fsub_(yj,yi), dz = fsub_(zj,zi);
    return fadd_(fadd_(fmul_(dx,dx), fmul_(dy,dy)), fmul_(dz,dz));
}

// ---- FP32 Cody-Waite 2pi reduction ----
#define INV_2PI  0.15915494309189535f
#define PI2_C1   6.2831855f
#define PI2_C2  -1.7484555e-07f
#define PI2_C3  -5.4469782e-15f
__device__ __forceinline__ float red2pi_(float ang){
    float k = rintf(ang * INV_2PI);
    float r = fmaf(-k, PI2_C1, ang);
    r = fmaf(-k, PI2_C2, r);
    r = fmaf(-k, PI2_C3, r);
    return r;
}

// ---- per-node orientation matrix + AD (fused into knn) ----
__device__ void node_work(const float* __restrict__ X, float* __restrict__ outAD, int id){
    int b = id / NN, n = id % NN;

    float O0=0,O1=0,O2=0,O3v=0,O4=0,O5=0,O6=0,O7=0,O8=0;
    float a0=0,a1=0,a2=0;

    if (n >= 1 && n <= NN-3){
        const float* Xb = X + b*NN*3;
        float p0x=Xb[(n-1)*3+0], p0y=Xb[(n-1)*3+1], p0z=Xb[(n-1)*3+2];
        float p1x=Xb[(n  )*3+0], p1y=Xb[(n  )*3+1], p1z=Xb[(n  )*3+2];
        float p2x=Xb[(n+1)*3+0], p2y=Xb[(n+1)*3+1], p2z=Xb[(n+1)*3+2];
        float p3x=Xb[(n+2)*3+0], p3y=Xb[(n+2)*3+1], p3z=Xb[(n+2)*3+2];

        float u2x=fsub_(p1x,p0x), u2y=fsub_(p1y,p0y), u2z=fsub_(p1z,p0z); norm3_(u2x,u2y,u2z);
        float u1x=fsub_(p2x,p1x), u1y=fsub_(p2y,p1y), u1z=fsub_(p2z,p1z); norm3_(u1x,u1y,u1z);
        float u0x=fsub_(p3x,p2x), u0y=fsub_(p3y,p2y), u0z=fsub_(p3z,p2z); norm3_(u0x,u0y,u0z);

        float n2x,n2y,n2z; cross3_(u2x,u2y,u2z,u1x,u1y,u1z,n2x,n2y,n2z); norm3_(n2x,n2y,n2z);
        float n1x,n1y,n1z; cross3_(u1x,u1y,u1z,u0x,u0y,u0z,n1x,n1y,n1z); norm3_(n1x,n1y,n1z);

        const float lo = (float)(-1.0 + 1e-6);
        const float hi = (float)( 1.0 - 1e-6);
        float cosA = fminf(fmaxf(-dot3_(u1x,u1y,u1z,u0x,u0y,u0z), lo), hi);
        float A = acosf(cosA);
        float cosD = fminf(fmaxf(dot3_(n2x,n2y,n2z,n1x,n1y,n1z), lo), hi);
        float s = dot3_(u2x,u2y,u2z,n1x,n1y,n1z);
        float sg = (s > 0.0f) ? 1.0f : ((s < 0.0f) ? -1.0f : 0.0f);
        float Dang = fmul_(sg, acosf(cosD));

        float sA = sinf(A);
        a0 = cosf(A);
        a1 = fmul_(sA, cosf(Dang));
        a2 = fmul_(sA, sinf(Dang));

        float o1x=fsub_(u2x,u1x), o1y=fsub_(u2y,u1y), o1z=fsub_(u2z,u1z); norm3_(o1x,o1y,o1z);
        float cx,cy,cz; cross3_(o1x,o1y,o1z,n2x,n2y,n2z,cx,cy,cz);
        O0=o1x; O1=o1y; O2=o1z; O3v=n2x; O4=n2y; O5=n2z; O6=cx; O7=cy; O8=cz;
    }
    float* Om = g_Omat + id*9;
    Om[0]=O0; Om[1]=O1; Om[2]=O2; Om[3]=O3v; Om[4]=O4; Om[5]=O5; Om[6]=O6; Om[7]=O7; Om[8]=O8;
    outAD[id*3+0]=a0; outAD[id*3+1]=a1; outAD[id*3+2]=a2;
}

// ============================================================================
// Kernel A v5: exact top-30 kNN + fused node work.
// 2 rows/warp, 8 rows/block. Pass 1 computes exact-d2 octave bins once,
// packs them as nibbles into smem. Pass 2 is a nibble scan (no distance
// recompute). Rank-based extraction on exact (D, j) keys.
// ============================================================================
#define TPB5 128
#define RW   2
#define RB   8
#define CAP5 192

__global__ __launch_bounds__(TPB5, 8) void knn_kernel(
    const float* __restrict__ X, float* __restrict__ outD, float* __restrict__ outE,
    float* __restrict__ outAD)
{
    __shared__ unsigned int       binsS[RB][512];   // 16KB nibble-packed bins
    __shared__ unsigned long long cand[RB][CAP5];   // 12KB

    const int t = threadIdx.x, w = t >> 5, lane = t & 31;
    const int blk = blockIdx.x;
    const int b   = blk / (NN/RB);
    const int r0  = (blk % (NN/RB))*RB + w*RW;
    const float* Xb = X + b*NN*3;

    // fused node work: 8 node ids per block
    if (t < 16){
        if (t < 8) node_work(X, outAD, blk*8 + t);
        if (blk == 0){
            if (t < 8){
                float argf = __fmul_rn((float)(2*t), -0.5756462732485115f);
                g_freq[t] = (float)exp((double)argf);
            }
            if (t < 15) g_mu[t] = (float)((double)t * (20.0/14.0));
        }
    }

    float xi[RW], yi[RW], zi[RW];
    #pragma unroll
    for (int r = 0; r < RW; r++){
        xi[r] = Xb[(r0+r)*3+0];
        yi[r] = Xb[(r0+r)*3+1];
        zi[r] = Xb[(r0+r)*3+2];
    }

    unsigned long long h0[RW], h1[RW];
    #pragma unroll
    for (int r = 0; r < RW; r++){ h0[r]=0ull; h1[r]=0ull; }

    // ---- pass 1: exact-d2 octave bins -> register hist + smem nibble cache ----
    for (int mm = 0; mm < 16; mm++){
        const float4* p = (const float4*)Xb + mm*192 + lane*6;
        float4 v0=p[0], v1=p[1], v2=p[2], v3=p[3], v4=p[4], v5=p[5];
        float a[24] = {v0.x,v0.y,v0.z,v0.w, v1.x,v1.y,v1.z,v1.w,
                       v2.x,v2.y,v2.z,v2.w, v3.x,v3.y,v3.z,v3.w,
                       v4.x,v4.y,v4.z,v4.w, v5.x,v5.y,v5.z,v5.w};
        unsigned int nib[RW];
        #pragma unroll
        for (int r = 0; r < RW; r++) nib[r] = 0u;
        #pragma unroll
        for (int jj = 0; jj < 8; jj++){
            float xj = a[jj*3], yj = a[jj*3+1], zj = a[jj*3+2];
            #pragma unroll
            for (int r = 0; r < RW; r++){
                float d2 = d2_exact(xi[r],yi[r],zi[r],xj,yj,zj);
                int bin = (int)(__float_as_uint(d2) >> 23) - 126;
                bin = max(0, min(15, bin));
                unsigned long long one = 1ull << ((bin & 7) << 3);
                if (bin < 8) h0[r] += one; else h1[r] += one;
                nib[r] |= (unsigned int)bin << (jj*4);
            }
        }
        #pragma unroll
        for (int r = 0; r < RW; r++)
            binsS[w*RW + r][mm*32 + lane] = nib[r];
    }

    // ---- per-row threshold bin via warp tree over packed counters ----
    int Tb[RW];
    const unsigned long long M8 = 0x00FF00FF00FF00FFull;
    #pragma unroll
    for (int r = 0; r < RW; r++){
        unsigned long long a0 =  h0[r]       & M8;
        unsigned long long a1 = (h0[r] >> 8) & M8;
        unsigned long long a2 =  h1[r]       & M8;
        unsigned long long a3 = (h1[r] >> 8) & M8;
        #pragma unroll
        for (int off = 16; off; off >>= 1){
            a0 += __shfl_xor_sync(0xffffffffu, a0, off);
            a1 += __shfl_xor_sync(0xffffffffu, a1, off);
            a2 += __shfl_xor_sync(0xffffffffu, a2, off);
            a3 += __shfl_xor_sync(0xffffffffu, a3, off);
        }
        int cum = 0, T = 15;
        #pragma unroll
        for (int bb = 0; bb < 16; bb++){
            unsigned long long src = (bb < 8) ? ((bb & 1) ? a1 : a0)
                                              : ((bb & 1) ? a3 : a2);
            cum += (int)((src >> (((bb >> 1) & 3) << 4)) & 0xFFFFull);
            if (cum >= KK){ T = bb; break; }
        }
        Tb[r] = T;
    }
    __syncwarp();

    // ---- pass 2: nibble scan -> compact survivor indices ----
    int cnt[RW];
    #pragma unroll
    for (int r = 0; r < RW; r++){
        const int row = w*RW + r;
        const unsigned int Tr = (unsigned int)Tb[r];
        unsigned int wd[16];
        int local = 0;
        #pragma unroll
        for (int u = 0; u < 16; u++){
            wd[u] = binsS[row][lane + 32*u];
            #pragma unroll
            for (int k = 0; k < 8; k++)
                local += (int)(((wd[u] >> (k*4)) & 15u) <= Tr);
        }
        // warp exclusive scan of local counts
        int cum = local;
        #pragma unroll
        for (int off = 1; off < 32; off <<= 1){
            int v = __shfl_up_sync(0xffffffffu, cum, off);
            if (lane >= off) cum += v;
        }
        int pos = cum - local;
        cnt[r] = __shfl_sync(0xffffffffu, cum, 31);
        #pragma unroll
        for (int u = 0; u < 16; u++){
            #pragma unroll
            for (int k = 0; k < 8; k++){
                if (((wd[u] >> (k*4)) & 15u) <= Tr){
                    if (pos < CAP5)
                        cand[row][pos] = (unsigned long long)((lane + 32*u)*8 + k);
                    pos++;
                }
            }
        }
    }
    __syncwarp();

    // ---- extraction: exact (D, j) keys + rank-based selection ----
    #pragma unroll
    for (int r = 0; r < RW; r++){
        const int row = w*RW + r;
        const int c = min(cnt[r], CAP5);
        const int base = (b*NN + r0 + r)*KK;

        for (int idx = lane; idx < c; idx += 32){
            unsigned int j = (unsigned int)cand[row][idx];
            float xj = __ldg(&Xb[j*3+0]);
            float yj = __ldg(&Xb[j*3+1]);
            float zj = __ldg(&Xb[j*3+2]);
            float d2 = d2_exact(xi[r],yi[r],zi[r],xj,yj,zj);
            float D  = __fsqrt_rn(fadd_(d2, 1e-6f));
            cand[row][idx] = ((unsigned long long)__float_as_uint(D) << 32) | j;
        }
        __syncwarp();

        for (int idx = lane; idx < c; idx += 32){
            unsigned long long k = cand[row][idx];
            int rank = 0;
            for (int cc = 0; cc < c; cc++)
                rank += (cand[row][cc] < k) ? 1 : 0;
            if (rank < KK){
                unsigned int jj = (unsigned int)(k & 0xFFFFFFFFull);
                outD[base + rank]   = __uint_as_float((unsigned int)(k >> 32));
                outE[base + rank]   = (float)jj;
                g_eidx[base + rank] = (int)jj;
            }
        }
        __syncwarp();
    }
}

// ============================================================================
// Kernel C1: positional encodings, one thread per output element (coalesced)
// ============================================================================
__global__ __launch_bounds__(256) void pos_kernel(float* __restrict__ outP){
    int id = blockIdx.x*blockDim.x + threadIdx.x;
    if (id >= SZ_POS) return;
    int m = id & 15;
    int e = id >> 4;
    int i = (e / KK) % NN;
    int j = g_eidx[e];
    float d = fsub_((float)j, (float)i);
    float ang = fmul_(d, g_freq[m & 7]);
    float r = red2pi_(ang);
    outP[id] = (m < 8) ? __cosf(r) : __sinf(r);
}

// ============================================================================
// Kernel C2: gaussian smearing, one thread per output element (coalesced)
// ============================================================================
__global__ __launch_bounds__(256) void gs_kernel(
    const float* __restrict__ Dn, float* __restrict__ outG)
{
    int id = blockIdx.x*blockDim.x + threadIdx.x;
    if (id >= SZ_GS) return;
    int q = id / 15;
    int m = id - q*15;
    float D  = __ldg(&Dn[q]);
    float tt = fsub_(D, g_mu[m]) * 0.74999998f;   // 1/sigma (f32-exact recip)
    outG[id] = __expf(-tt*tt);
}

// ============================================================================
// Kernel C3: dU = normalize(O @ (X_nb - X_i))   (B,N,K,3)
// ============================================================================
__global__ __launch_bounds__(256) void du_kernel(
    const float* __restrict__ X, float* __restrict__ outO)
{
    int id = blockIdx.x*blockDim.x + threadIdx.x;
    if (id >= BB*NN*KK) return;
    int ni = id / KK;
    int i  = ni % NN;
    int b  = ni / NN;
    int j  = g_eidx[id];
    const float* Xb = X + b*NN*3;
    float dx = fsub_(Xb[j*3+0], Xb[i*3+0]);
    float dy = fsub_(Xb[j*3+1], Xb[i*3+1]);
    float dz = fsub_(Xb[j*3+2], Xb[i*3+2]);
    const float* Om = g_Omat + (size_t)ni*9;
    float v0 = dot3_(Om[0],Om[1],Om[2], dx,dy,dz);
    float v1 = dot3_(Om[3],Om[4],Om[5], dx,dy,dz);
    float v2 = dot3_(Om[6],Om[7],Om[8], dx,dy,dz);
    float n = __fsqrt_rn(dot3_(v0,v1,v2,v0,v1,v2));
    n = fmaxf(n, 1e-12f);
    outO[(size_t)id*3+0] = __fdiv_rn(v0,n);
    outO[(size_t)id*3+1] = __fdiv_rn(v1,n);
    outO[(size_t)id*3+2] = __fdiv_rn(v2,n);
}

// ============================================================================
extern "C" void kernel_launch(void* const* d_in, const int* in_sizes, int n_in,
                              void* d_out, int out_size)
{
    const float* X = (const float*)d_in[0];
    float* out = (float*)d_out;

    knn_kernel<<<BB*NN/RB, TPB5>>>(X, out + OFF_DN, out + OFF_EI, out + OFF_AD);
    pos_kernel<<<(SZ_POS + 255)/256, 256>>>(out + OFF_POS);
    gs_kernel<<<(SZ_GS + 255)/256, 256>>>(out + OFF_DN, out + OFF_GS);
    du_kernel<<<(BB*NN*KK + 255)/256, 256>>>(X, out + OFF_OF);
}

// round 8
// speedup vs baseline: 1.3390x; 1.3390x over previous
#include <cuda_runtime.h>
#include <math.h>

#define BB 2
#define NN 4096
#define KK 30

#define SZ_POS (BB*NN*KK*16)
#define SZ_AD  (BB*NN*3)
#define SZ_OF  (BB*NN*KK*3)
#define SZ_GS  (BB*NN*KK*15)
#define SZ_DN  (BB*NN*KK)

#define OFF_POS 0
#define OFF_AD  (OFF_POS + SZ_POS)
#define OFF_OF  (OFF_AD  + SZ_AD)
#define OFF_GS  (OFF_OF  + SZ_OF)
#define OFF_DN  (OFF_GS  + SZ_GS)
#define OFF_EI  (OFF_DN  + SZ_DN)

// ---- scratch (no allocations allowed) ----
static __device__ int   g_eidx[BB*NN*KK];
static __device__ float g_Omat[BB*NN*9];
static __device__ float g_freq[8];
static __device__ float g_mu[15];

// ---- exact-rounding helpers ----
__device__ __forceinline__ float fadd_(float a, float b){ return __fadd_rn(a,b); }
__device__ __forceinline__ float fsub_(float a, float b){ return __fsub_rn(a,b); }
__device__ __forceinline__ float fmul_(float a, float b){ return __fmul_rn(a,b); }
__device__ __forceinline__ float dot3_(float ax,float ay,float az,
                                       float bx,float by,float bz){
    return fadd_(fadd_(fmul_(ax,bx), fmul_(ay,by)), fmul_(az,bz));
}
__device__ __forceinline__ void norm3_(float &x, float &y, float &z){
    float n = __fsqrt_rn(dot3_(x,y,z,x,y,z));
    n = fmaxf(n, 1e-12f);
    x = __fdiv_rn(x,n); y = __fdiv_rn(y,n); z = __fdiv_rn(z,n);
}
__device__ __forceinline__ void cross3_(float ax,float ay,float az,
                                        float bx,float by,float bz,
                                        float &cx,float &cy,float &cz){
    cx = fsub_(fmul_(ay,bz), fmul_(az,by));
    cy = fsub_(fmul_(az,bx), fmul_(ax,bz));
    cz = fsub_(fmul_(ax,by), fmul_(ay,bx));
}
__device__ __forceinline__ float d2_exact(float xi,float yi,float zi,
                                          float xj,float yj,float zj){
    float dx = fsub_(xj,xi), dy = fsub_(yj,yi), dz = fsub_(zj,zi);
    return fadd_(fadd_(fmul_(dx,dx), fmul_(dy,dy)), fmul_(dz,dz));
}

// ---- FP32 Cody-Waite 2pi reduction ----
#define INV_2PI  0.15915494309189535f
#define PI2_C1   6.2831855f
#define PI2_C2  -1.7484555e-07f
#define PI2_C3  -5.4469782e-15f
__device__ __forceinline__ float red2pi_(float ang){
    float k = rintf(ang * INV_2PI);
    float r = fmaf(-k, PI2_C1, ang);
    r = fmaf(-k, PI2_C2, r);
    r = fmaf(-k, PI2_C3, r);
    return r;
}

// ---- per-node orientation matrix + AD (fused into knn) ----
__device__ void node_work(const float* __restrict__ X, float* __restrict__ outAD, int id){
    int b = id / NN, n = id % NN;

    float O0=0,O1=0,O2=0,O3v=0,O4=0,O5=0,O6=0,O7=0,O8=0;
    float a0=0,a1=0,a2=0;

    if (n >= 1 && n <= NN-3){
        const float* Xb = X + b*NN*3;
        float p0x=Xb[(n-1)*3+0], p0y=Xb[(n-1)*3+1], p0z=Xb[(n-1)*3+2];
        float p1x=Xb[(n  )*3+0], p1y=Xb[(n  )*3+1], p1z=Xb[(n  )*3+2];
        float p2x=Xb[(n+1)*3+0], p2y=Xb[(n+1)*3+1], p2z=Xb[(n+1)*3+2];
        float p3x=Xb[(n+2)*3+0], p3y=Xb[(n+2)*3+1], p3z=Xb[(n+2)*3+2];

        float u2x=fsub_(p1x,p0x), u2y=fsub_(p1y,p0y), u2z=fsub_(p1z,p0z); norm3_(u2x,u2y,u2z);
        float u1x=fsub_(p2x,p1x), u1y=fsub_(p2y,p1y), u1z=fsub_(p2z,p1z); norm3_(u1x,u1y,u1z);
        float u0x=fsub_(p3x,p2x), u0y=fsub_(p3y,p2y), u0z=fsub_(p3z,p2z); norm3_(u0x,u0y,u0z);

        float n2x,n2y,n2z; cross3_(u2x,u2y,u2z,u1x,u1y,u1z,n2x,n2y,n2z); norm3_(n2x,n2y,n2z);
        float n1x,n1y,n1z; cross3_(u1x,u1y,u1z,u0x,u0y,u0z,n1x,n1y,n1z); norm3_(n1x,n1y,n1z);

        const float lo = (float)(-1.0 + 1e-6);
        const float hi = (float)( 1.0 - 1e-6);
        float cosA = fminf(fmaxf(-dot3_(u1x,u1y,u1z,u0x,u0y,u0z), lo), hi);
        float A = acosf(cosA);
        float cosD = fminf(fmaxf(dot3_(n2x,n2y,n2z,n1x,n1y,n1z), lo), hi);
        float s = dot3_(u2x,u2y,u2z,n1x,n1y,n1z);
        float sg = (s > 0.0f) ? 1.0f : ((s < 0.0f) ? -1.0f : 0.0f);
        float Dang = fmul_(sg, acosf(cosD));

        float sA = sinf(A);
        a0 = cosf(A);
        a1 = fmul_(sA, cosf(Dang));
        a2 = fmul_(sA, sinf(Dang));

        float o1x=fsub_(u2x,u1x), o1y=fsub_(u2y,u1y), o1z=fsub_(u2z,u1z); norm3_(o1x,o1y,o1z);
        float cx,cy,cz; cross3_(o1x,o1y,o1z,n2x,n2y,n2z,cx,cy,cz);
        O0=o1x; O1=o1y; O2=o1z; O3v=n2x; O4=n2y; O5=n2z; O6=cx; O7=cy; O8=cz;
    }
    float* Om = g_Omat + id*9;
    Om[0]=O0; Om[1]=O1; Om[2]=O2; Om[3]=O3v; Om[4]=O4; Om[5]=O5; Om[6]=O6; Om[7]=O7; Om[8]=O8;
    outAD[id*3+0]=a0; outAD[id*3+1]=a1; outAD[id*3+2]=a2;
}

// ============================================================================
// Kernel A v6: exact top-30 kNN.  v1 structure (thread = point, 8 rows/block
// register-resident, coalesced loads) + nibble bin cache (no atomics in the
// hot loop, no pass-2 distance recompute) + rank-based extraction.
// ============================================================================
#define TPB6 256
#define RB6  8
#define CAP6 192

__global__ __launch_bounds__(TPB6) void knn_kernel(
    const float* __restrict__ X, float* __restrict__ outD, float* __restrict__ outE,
    float* __restrict__ outAD)
{
    __shared__ unsigned int       nib[NN];          // 16KB: 8 row-bins per point
    __shared__ unsigned long long cand[RB6][CAP6];  // 12KB
    __shared__ int scnt[RB6];
    __shared__ int sTb[RB6];

    const int t = threadIdx.x, w = t >> 5, lane = t & 31;
    const int blk = blockIdx.x;
    const int b   = blk / (NN/RB6);
    const int r0  = (blk % (NN/RB6))*RB6;
    const float* Xb = X + b*NN*3;

    if (t < RB6){
        node_work(X, outAD, blk*RB6 + t);
        scnt[t] = 0;
    }
    if (blk == 0 && t >= 32 && t < 64){
        int u = t - 32;
        if (u < 8){
            float argf = __fmul_rn((float)(2*u), -0.5756462732485115f);
            g_freq[u] = (float)exp((double)argf);
        }
        if (u < 15) g_mu[u] = (float)((double)u * (20.0/14.0));
    }

    float xi[RB6], yi[RB6], zi[RB6];
    #pragma unroll
    for (int r = 0; r < RB6; r++){
        xi[r] = Xb[(r0+r)*3+0];
        yi[r] = Xb[(r0+r)*3+1];
        zi[r] = Xb[(r0+r)*3+2];
    }
    __syncthreads();

    // ---- pass 1: exact-d2 octave bin per (row, point), packed nibbles ----
    #pragma unroll 2
    for (int m = 0; m < NN/TPB6; m++){
        int j = m*TPB6 + t;
        float xj = __ldg(&Xb[j*3+0]);
        float yj = __ldg(&Xb[j*3+1]);
        float zj = __ldg(&Xb[j*3+2]);
        unsigned int nb = 0u;
        #pragma unroll
        for (int r = 0; r < RB6; r++){
            float d2 = d2_exact(xi[r],yi[r],zi[r],xj,yj,zj);
            int bin = (int)(__float_as_uint(d2) >> 23) - 126;
            bin = max(0, min(15, bin));
            nb |= (unsigned int)bin << (r*4);
        }
        nib[j] = nb;
    }
    __syncthreads();

    // ---- pass 1.5: warp w builds row-w histogram from nibble cache ----
    {
        unsigned int h0=0u, h1=0u, h2=0u, h3=0u;   // 16 bins x u8
        const int sh = w*4;
        #pragma unroll 4
        for (int u = 0; u < NN/32; u++){
            unsigned int bin = (nib[u*32 + lane] >> sh) & 15u;
            unsigned int add = 1u << ((bin & 3u) << 3);
            unsigned int sel = bin >> 2;
            if      (sel == 0u) h0 += add;
            else if (sel == 1u) h1 += add;
            else if (sel == 2u) h2 += add;
            else                h3 += add;
        }
        // widen u8 -> u16 fields, warp-reduce
        unsigned int v[8];
        v[0]= h0      & 0x00FF00FFu; v[1]=(h0>>8) & 0x00FF00FFu;
        v[2]= h1      & 0x00FF00FFu; v[3]=(h1>>8) & 0x00FF00FFu;
        v[4]= h2      & 0x00FF00FFu; v[5]=(h2>>8) & 0x00FF00FFu;
        v[6]= h3      & 0x00FF00FFu; v[7]=(h3>>8) & 0x00FF00FFu;
        #pragma unroll
        for (int off = 16; off; off >>= 1){
            #pragma unroll
            for (int q = 0; q < 8; q++)
                v[q] += __shfl_xor_sync(0xffffffffu, v[q], off);
        }
        int cum = 0, T = 15;
        #pragma unroll
        for (int i = 0; i < 16; i++){
            unsigned int word = v[(i>>2)*2 + (i&1)];
            cum += (int)((word >> (((i>>1)&1)*16)) & 0xFFFFu);
            if (cum >= KK){ T = i; break; }
        }
        if (lane == 0) sTb[w] = T;
    }
    __syncthreads();

    int Tl[RB6];
    #pragma unroll
    for (int r = 0; r < RB6; r++) Tl[r] = sTb[r];

    // ---- pass 2: nibble scan, compact survivor indices (rare atomics) ----
    #pragma unroll 2
    for (int m = 0; m < NN/TPB6; m++){
        int j = m*TPB6 + t;
        unsigned int nb = nib[j];
        #pragma unroll
        for (int r = 0; r < RB6; r++){
            if ((int)((nb >> (r*4)) & 15u) <= Tl[r]){
                int pos = atomicAdd(&scnt[r], 1);
                if (pos < CAP6) cand[r][pos] = (unsigned long long)j;
            }
        }
    }
    __syncthreads();

    // ---- extraction: warp w, row w; exact (D, j) keys + rank selection ----
    {
        const int row = r0 + w;
        const int c = min(scnt[w], CAP6);
        const int base = (b*NN + row)*KK;
        const float xr = Xb[row*3+0], yr = Xb[row*3+1], zr = Xb[row*3+2];

        for (int idx = lane; idx < c; idx += 32){
            unsigned int j = (unsigned int)cand[w][idx];
            float xj = __ldg(&Xb[j*3+0]);
            float yj = __ldg(&Xb[j*3+1]);
            float zj = __ldg(&Xb[j*3+2]);
            float d2 = d2_exact(xr,yr,zr,xj,yj,zj);
            float D  = __fsqrt_rn(fadd_(d2, 1e-6f));
            cand[w][idx] = ((unsigned long long)__float_as_uint(D) << 32) | j;
        }
        __syncwarp();

        for (int idx = lane; idx < c; idx += 32){
            unsigned long long k = cand[w][idx];
            int rank = 0;
            for (int cc = 0; cc < c; cc++)
                rank += (cand[w][cc] < k) ? 1 : 0;
            if (rank < KK){
                unsigned int jj = (unsigned int)(k & 0xFFFFFFFFull);
                outD[base + rank]   = __uint_as_float((unsigned int)(k >> 32));
                outE[base + rank]   = (float)jj;
                g_eidx[base + rank] = (int)jj;
            }
        }
    }
}

// ============================================================================
// Kernel C1: positional encodings, one thread per output element (coalesced)
// ============================================================================
__global__ __launch_bounds__(256) void pos_kernel(float* __restrict__ outP){
    int id = blockIdx.x*blockDim.x + threadIdx.x;
    if (id >= SZ_POS) return;
    int m = id & 15;
    int e = id >> 4;
    int i = (e / KK) % NN;
    int j = g_eidx[e];
    float d = fsub_((float)j, (float)i);
    float ang = fmul_(d, g_freq[m & 7]);
    float r = red2pi_(ang);
    outP[id] = (m < 8) ? __cosf(r) : __sinf(r);
}

// ============================================================================
// Kernel C2: gaussian smearing, one thread per output element (coalesced)
// ============================================================================
__global__ __launch_bounds__(256) void gs_kernel(
    const float* __restrict__ Dn, float* __restrict__ outG)
{
    int id = blockIdx.x*blockDim.x + threadIdx.x;
    if (id >= SZ_GS) return;
    int q = id / 15;
    int m = id - q*15;
    float D  = __ldg(&Dn[q]);
    float tt = fsub_(D, g_mu[m]) * 0.74999998f;
    outG[id] = __expf(-tt*tt);
}

// ============================================================================
// Kernel C3: dU = normalize(O @ (X_nb - X_i))   (B,N,K,3)
// ============================================================================
__global__ __launch_bounds__(256) void du_kernel(
    const float* __restrict__ X, float* __restrict__ outO)
{
    int id = blockIdx.x*blockDim.x + threadIdx.x;
    if (id >= BB*NN*KK) return;
    int ni = id / KK;
    int i  = ni % NN;
    int b  = ni / NN;
    int j  = g_eidx[id];
    const float* Xb = X + b*NN*3;
    float dx = fsub_(Xb[j*3+0], Xb[i*3+0]);
    float dy = fsub_(Xb[j*3+1], Xb[i*3+1]);
    float dz = fsub_(Xb[j*3+2], Xb[i*3+2]);
    const float* Om = g_Omat + (size_t)ni*9;
    float v0 = dot3_(Om[0],Om[1],Om[2], dx,dy,dz);
    float v1 = dot3_(Om[3],Om[4],Om[5], dx,dy,dz);
    float v2 = dot3_(Om[6],Om[7],Om[8], dx,dy,dz);
    float n = __fsqrt_rn(dot3_(v0,v1,v2,v0,v1,v2));
    n = fmaxf(n, 1e-12f);
    outO[(size_t)id*3+0] = __fdiv_rn(v0,n);
    outO[(size_t)id*3+1] = __fdiv_rn(v1,n);
    outO[(size_t)id*3+2] = __fdiv_rn(v2,n);
}

// ============================================================================
extern "C" void kernel_launch(void* const* d_in, const int* in_sizes, int n_in,
                              void* d_out, int out_size)
{
    const float* X = (const float*)d_in[0];
    float* out = (float*)d_out;

    knn_kernel<<<BB*NN/RB6, TPB6>>>(X, out + OFF_DN, out + OFF_EI, out + OFF_AD);
    pos_kernel<<<(SZ_POS + 255)/256, 256>>>(out + OFF_POS);
    gs_kernel<<<(SZ_GS + 255)/256, 256>>>(out + OFF_DN, out + OFF_GS);
    du_kernel<<<(BB*NN*KK + 255)/256, 256>>>(X, out + OFF_OF);
}

// round 9
// speedup vs baseline: 1.4306x; 1.0684x over previous
#include <cuda_runtime.h>
#include <math.h>

#define BB 2
#define NN 4096
#define KK 30

#define SZ_POS (BB*NN*KK*16)
#define SZ_AD  (BB*NN*3)
#define SZ_OF  (BB*NN*KK*3)
#define SZ_GS  (BB*NN*KK*15)
#define SZ_DN  (BB*NN*KK)

#define OFF_POS 0
#define OFF_AD  (OFF_POS + SZ_POS)
#define OFF_OF  (OFF_AD  + SZ_AD)
#define OFF_GS  (OFF_OF  + SZ_OF)
#define OFF_DN  (OFF_GS  + SZ_GS)
#define OFF_EI  (OFF_DN  + SZ_DN)

// ---- exact-rounding helpers (used for all OUTPUT values) ----
__device__ __forceinline__ float fadd_(float a, float b){ return __fadd_rn(a,b); }
__device__ __forceinline__ float fsub_(float a, float b){ return __fsub_rn(a,b); }
__device__ __forceinline__ float fmul_(float a, float b){ return __fmul_rn(a,b); }
__device__ __forceinline__ float dot3_(float ax,float ay,float az,
                                       float bx,float by,float bz){
    return fadd_(fadd_(fmul_(ax,bx), fmul_(ay,by)), fmul_(az,bz));
}
__device__ __forceinline__ void norm3_(float &x, float &y, float &z){
    float n = __fsqrt_rn(dot3_(x,y,z,x,y,z));
    n = fmaxf(n, 1e-12f);
    x = __fdiv_rn(x,n); y = __fdiv_rn(y,n); z = __fdiv_rn(z,n);
}
__device__ __forceinline__ void cross3_(float ax,float ay,float az,
                                        float bx,float by,float bz,
                                        float &cx,float &cy,float &cz){
    cx = fsub_(fmul_(ay,bz), fmul_(az,by));
    cy = fsub_(fmul_(az,bx), fmul_(ax,bz));
    cz = fsub_(fmul_(ax,by), fmul_(ay,bx));
}
__device__ __forceinline__ float d2_exact(float xi,float yi,float zi,
                                          float xj,float yj,float zj){
    float dx = fsub_(xj,xi), dy = fsub_(yj,yi), dz = fsub_(zj,zi);
    return fadd_(fadd_(fmul_(dx,dx), fmul_(dy,dy)), fmul_(dz,dz));
}

// ---- FP32 Cody-Waite 2pi reduction ----
#define INV_2PI  0.15915494309189535f
#define PI2_C1   6.2831855f
#define PI2_C2  -1.7484555e-07f
#define PI2_C3  -5.4469782e-15f
__device__ __forceinline__ float red2pi_(float ang){
    float k = rintf(ang * INV_2PI);
    float r = fmaf(-k, PI2_C1, ang);
    r = fmaf(-k, PI2_C2, r);
    r = fmaf(-k, PI2_C3, r);
    return r;
}

// ---- per-node orientation matrix + AD ----
__device__ void node_work(const float* __restrict__ X, float* __restrict__ outAD,
                          int id, float* __restrict__ sOmRow){
    int b = id / NN, n = id % NN;

    float O0=0,O1=0,O2=0,O3v=0,O4=0,O5=0,O6=0,O7=0,O8=0;
    float a0=0,a1=0,a2=0;

    if (n >= 1 && n <= NN-3){
        const float* Xb = X + b*NN*3;
        float p0x=Xb[(n-1)*3+0], p0y=Xb[(n-1)*3+1], p0z=Xb[(n-1)*3+2];
        float p1x=Xb[(n  )*3+0], p1y=Xb[(n  )*3+1], p1z=Xb[(n  )*3+2];
        float p2x=Xb[(n+1)*3+0], p2y=Xb[(n+1)*3+1], p2z=Xb[(n+1)*3+2];
        float p3x=Xb[(n+2)*3+0], p3y=Xb[(n+2)*3+1], p3z=Xb[(n+2)*3+2];

        float u2x=fsub_(p1x,p0x), u2y=fsub_(p1y,p0y), u2z=fsub_(p1z,p0z); norm3_(u2x,u2y,u2z);
        float u1x=fsub_(p2x,p1x), u1y=fsub_(p2y,p1y), u1z=fsub_(p2z,p1z); norm3_(u1x,u1y,u1z);
        float u0x=fsub_(p3x,p2x), u0y=fsub_(p3y,p2y), u0z=fsub_(p3z,p2z); norm3_(u0x,u0y,u0z);

        float n2x,n2y,n2z; cross3_(u2x,u2y,u2z,u1x,u1y,u1z,n2x,n2y,n2z); norm3_(n2x,n2y,n2z);
        float n1x,n1y,n1z; cross3_(u1x,u1y,u1z,u0x,u0y,u0z,n1x,n1y,n1z); norm3_(n1x,n1y,n1z);

        const float lo = (float)(-1.0 + 1e-6);
        const float hi = (float)( 1.0 - 1e-6);
        float cosA = fminf(fmaxf(-dot3_(u1x,u1y,u1z,u0x,u0y,u0z), lo), hi);
        float A = acosf(cosA);
        float cosD = fminf(fmaxf(dot3_(n2x,n2y,n2z,n1x,n1y,n1z), lo), hi);
        float s = dot3_(u2x,u2y,u2z,n1x,n1y,n1z);
        float sg = (s > 0.0f) ? 1.0f : ((s < 0.0f) ? -1.0f : 0.0f);
        float Dang = fmul_(sg, acosf(cosD));

        float sA = sinf(A);
        a0 = cosf(A);
        a1 = fmul_(sA, cosf(Dang));
        a2 = fmul_(sA, sinf(Dang));

        float o1x=fsub_(u2x,u1x), o1y=fsub_(u2y,u1y), o1z=fsub_(u2z,u1z); norm3_(o1x,o1y,o1z);
        float cx,cy,cz; cross3_(o1x,o1y,o1z,n2x,n2y,n2z,cx,cy,cz);
        O0=o1x; O1=o1y; O2=o1z; O3v=n2x; O4=n2y; O5=n2z; O6=cx; O7=cy; O8=cz;
    }
    sOmRow[0]=O0; sOmRow[1]=O1; sOmRow[2]=O2; sOmRow[3]=O3v; sOmRow[4]=O4;
    sOmRow[5]=O5; sOmRow[6]=O6; sOmRow[7]=O7; sOmRow[8]=O8;
    outAD[id*3+0]=a0; outAD[id*3+1]=a1; outAD[id*3+2]=a2;
}

// ============================================================================
// Fused kernel: exact top-30 kNN (v6 structure, expanded-FMA binning with
// safety sliver) + node features + all edge features, one block = 8 rows.
// ============================================================================
#define TPB 256
#define RB  8
#define CAP 224
#define LOG2E 1.4426950408889634f

__global__ __launch_bounds__(TPB) void fused_kernel(
    const float* __restrict__ X, float* __restrict__ out)
{
    __shared__ unsigned int       nib[NN];        // 16KB: 8 row-bins per point
    __shared__ unsigned long long cand[RB][CAP];  // 14KB
    __shared__ float stD[RB][KK];
    __shared__ int   stI[RB][KK];
    __shared__ float sOm[RB][9];
    __shared__ float sThr[RB];
    __shared__ float sfreq[8];
    __shared__ float smu[15];
    __shared__ int   scnt[RB];

    float* outP  = out + OFF_POS;
    float* outAD = out + OFF_AD;
    float* outO  = out + OFF_OF;
    float* outG  = out + OFF_GS;
    float* outD  = out + OFF_DN;
    float* outE  = out + OFF_EI;

    const int t = threadIdx.x, w = t >> 5, lane = t & 31;
    const int blk = blockIdx.x;
    const int b   = blk / (NN/RB);
    const int r0  = (blk % (NN/RB))*RB;
    const float* Xb = X + b*NN*3;

    if (t < RB){
        node_work(X, outAD, b*NN + r0 + t, sOm[t]);
        scnt[t] = 0;
    }
    if (t >= 32 && t < 64){
        int u = t - 32;
        if (u < 8){
            float argf = __fmul_rn((float)(2*u), -0.5756462732485115f);
            sfreq[u] = (float)exp((double)argf);
        }
        if (u < 15) smu[u] = (float)((double)u * (20.0/14.0));
    }

    // row coords + row norms (expanded-form, same op order as point norms)
    float xr[RB], yr[RB], zr[RB], nr[RB];
    #pragma unroll
    for (int r = 0; r < RB; r++){
        xr[r] = Xb[(r0+r)*3+0];
        yr[r] = Xb[(r0+r)*3+1];
        zr[r] = Xb[(r0+r)*3+2];
        nr[r] = fmaf(zr[r],zr[r], fmaf(yr[r],yr[r], xr[r]*xr[r]));
    }
    __syncthreads();

    // ---- pass 1: fast-d2 octave bin per (row, point), packed nibbles ----
    #pragma unroll 2
    for (int m = 0; m < NN/TPB; m++){
        int j = m*TPB + t;
        float xj = __ldg(&Xb[j*3+0]);
        float yj = __ldg(&Xb[j*3+1]);
        float zj = __ldg(&Xb[j*3+2]);
        float nj = fmaf(zj,zj, fmaf(yj,yj, xj*xj));
        unsigned int nb = 0u;
        #pragma unroll
        for (int r = 0; r < RB; r++){
            float s  = fmaf(zr[r],zj, fmaf(yr[r],yj, xr[r]*xj));
            float d2 = fmaf(-2.0f, s, nr[r] + nj);
            d2 = fmaxf(d2, 0.0f);
            int bin = (int)(__float_as_uint(d2) >> 23) - 126;
            bin = max(0, min(15, bin));
            nb |= (unsigned int)bin << (r*4);
        }
        nib[j] = nb;
    }
    __syncthreads();

    // ---- pass 1.5: warp w builds row-w histogram from nibble cache ----
    {
        unsigned int h0=0u, h1=0u, h2=0u, h3=0u;   // 16 bins x u8
        const int sh = w*4;
        #pragma unroll 4
        for (int u = 0; u < NN/32; u++){
            unsigned int bin = (nib[u*32 + lane] >> sh) & 15u;
            unsigned int add = 1u << ((bin & 3u) << 3);
            unsigned int sel = bin >> 2;
            if      (sel == 0u) h0 += add;
            else if (sel == 1u) h1 += add;
            else if (sel == 2u) h2 += add;
            else                h3 += add;
        }
        unsigned int v[8];
        v[0]= h0      & 0x00FF00FFu; v[1]=(h0>>8) & 0x00FF00FFu;
        v[2]= h1      & 0x00FF00FFu; v[3]=(h1>>8) & 0x00FF00FFu;
        v[4]= h2      & 0x00FF00FFu; v[5]=(h2>>8) & 0x00FF00FFu;
        v[6]= h3      & 0x00FF00FFu; v[7]=(h3>>8) & 0x00FF00FFu;
        #pragma unroll
        for (int off = 16; off; off >>= 1){
            #pragma unroll
            for (int q = 0; q < 8; q++)
                v[q] += __shfl_xor_sync(0xffffffffu, v[q], off);
        }
        int cum = 0, T = 15;
        #pragma unroll
        for (int i = 0; i < 16; i++){
            unsigned int word = v[(i>>2)*2 + (i&1)];
            cum += (int)((word >> (((i>>1)&1)*16)) & 0xFFFFu);
            if (cum >= KK){ T = i; break; }
        }
        // threshold = 2^T * (1 + 1/64): sliver >> worst-case expansion error
        if (lane == 0)
            sThr[w] = __uint_as_float((unsigned int)((127 + T) << 23) | 0x020000u);
    }
    __syncthreads();

    float Tl[RB];
    #pragma unroll
    for (int r = 0; r < RB; r++) Tl[r] = sThr[r];

    // ---- pass 2: recompute fast-d2, keep below sliver threshold ----
    #pragma unroll 2
    for (int m = 0; m < NN/TPB; m++){
        int j = m*TPB + t;
        float xj = __ldg(&Xb[j*3+0]);
        float yj = __ldg(&Xb[j*3+1]);
        float zj = __ldg(&Xb[j*3+2]);
        float nj = fmaf(zj,zj, fmaf(yj,yj, xj*xj));
        #pragma unroll
        for (int r = 0; r < RB; r++){
            float s  = fmaf(zr[r],zj, fmaf(yr[r],yj, xr[r]*xj));
            float d2 = fmaf(-2.0f, s, nr[r] + nj);
            d2 = fmaxf(d2, 0.0f);
            if (d2 < Tl[r]){
                int pos = atomicAdd(&scnt[r], 1);
                if (pos < CAP) cand[r][pos] = (unsigned long long)j;
            }
        }
    }
    __syncthreads();

    // ---- extraction: warp w, row w; exact (D, j) keys + rank selection ----
    {
        const int row = r0 + w;
        const int c = min(scnt[w], CAP);
        const int base = (b*NN + row)*KK;
        const float xi = xr[w], yi = yr[w], zi = zr[w];

        for (int idx = lane; idx < c; idx += 32){
            unsigned int j = (unsigned int)cand[w][idx];
            float xj = __ldg(&Xb[j*3+0]);
            float yj = __ldg(&Xb[j*3+1]);
            float zj = __ldg(&Xb[j*3+2]);
            float d2 = d2_exact(xi,yi,zi,xj,yj,zj);
            float D  = __fsqrt_rn(fadd_(d2, 1e-6f));
            cand[w][idx] = ((unsigned long long)__float_as_uint(D) << 32) | j;
        }
        __syncwarp();

        for (int idx = lane; idx < c; idx += 32){
            unsigned long long k = cand[w][idx];
            int rank = 0;
            for (int cc = 0; cc < c; cc++)
                rank += (cand[w][cc] < k) ? 1 : 0;
            if (rank < KK){
                unsigned int jj = (unsigned int)(k & 0xFFFFFFFFull);
                float D = __uint_as_float((unsigned int)(k >> 32));
                outD[base + rank] = D;
                outE[base + rank] = (float)jj;
                stD[w][rank] = D;
                stI[w][rank] = (int)jj;
            }
        }
    }
    __syncthreads();

    // ---- edge phase A: positional encodings (8 rows x 30 x 16, coalesced) --
    for (int id = t; id < RB*KK*16; id += TPB){
        int r = id / (KK*16);
        int q = id - r*(KK*16);
        int k = q >> 4, m = q & 15;
        int i = r0 + r;
        int j = stI[r][k];
        float d = fsub_((float)j, (float)i);
        float ang = fmul_(d, sfreq[m & 7]);
        float rr = red2pi_(ang);
        outP[(size_t)(b*NN + i)*(KK*16) + q] = (m < 8) ? __cosf(rr) : __sinf(rr);
    }

    // ---- edge phase B: gaussian smearing (8 rows x 30 x 15, coalesced) ----
    for (int id = t; id < RB*KK*15; id += TPB){
        int r = id / (KK*15);
        int q = id - r*(KK*15);
        int k = q / 15, m = q - k*15;
        float D  = stD[r][k];
        float tt = fsub_(D, smu[m]) * 0.74999998f;
        outG[(size_t)(b*NN + r0 + r)*(KK*15) + q] = __expf(-tt*tt);
    }

    // ---- edge phase C: dU (8 rows x 30 edges) ----
    if (t < RB*KK){
        int r = t / KK, k = t - r*KK;
        int i = r0 + r;
        int j = stI[r][k];
        float dx = fsub_(Xb[j*3+0], Xb[i*3+0]);
        float dy = fsub_(Xb[j*3+1], Xb[i*3+1]);
        float dz = fsub_(Xb[j*3+2], Xb[i*3+2]);
        const float* Om = sOm[r];
        float v0 = dot3_(Om[0],Om[1],Om[2], dx,dy,dz);
        float v1 = dot3_(Om[3],Om[4],Om[5], dx,dy,dz);
        float v2 = dot3_(Om[6],Om[7],Om[8], dx,dy,dz);
        float n = __fsqrt_rn(dot3_(v0,v1,v2,v0,v1,v2));
        n = fmaxf(n, 1e-12f);
        size_t o = (size_t)((b*NN + i)*KK + k)*3;
        outO[o+0] = __fdiv_rn(v0,n);
        outO[o+1] = __fdiv_rn(v1,n);
        outO[o+2] = __fdiv_rn(v2,n);
    }
}

// ============================================================================
extern "C" void kernel_launch(void* const* d_in, const int* in_sizes, int n_in,
                              void* d_out, int out_size)
{
    const float* X = (const float*)d_in[0];
    float* out = (float*)d_out;
    fused_kernel<<<BB*NN/RB, TPB>>>(X, out);
}

// round 10
// speedup vs baseline: 1.5647x; 1.0937x over previous
#include <cuda_runtime.h>
#include <math.h>

#define BB 2
#define NN 4096
#define KK 30

#define SZ_POS (BB*NN*KK*16)
#define SZ_AD  (BB*NN*3)
#define SZ_OF  (BB*NN*KK*3)
#define SZ_GS  (BB*NN*KK*15)
#define SZ_DN  (BB*NN*KK)

#define OFF_POS 0
#define OFF_AD  (OFF_POS + SZ_POS)
#define OFF_OF  (OFF_AD  + SZ_AD)
#define OFF_GS  (OFF_OF  + SZ_OF)
#define OFF_DN  (OFF_GS  + SZ_GS)
#define OFF_EI  (OFF_DN  + SZ_DN)

// ---- exact-rounding helpers (used for OUTPUT values / selection keys) ----
__device__ __forceinline__ float fadd_(float a, float b){ return __fadd_rn(a,b); }
__device__ __forceinline__ float fsub_(float a, float b){ return __fsub_rn(a,b); }
__device__ __forceinline__ float fmul_(float a, float b){ return __fmul_rn(a,b); }
__device__ __forceinline__ float dot3_(float ax,float ay,float az,
                                       float bx,float by,float bz){
    return fadd_(fadd_(fmul_(ax,bx), fmul_(ay,by)), fmul_(az,bz));
}
__device__ __forceinline__ void norm3_(float &x, float &y, float &z){
    float n = __fsqrt_rn(dot3_(x,y,z,x,y,z));
    n = fmaxf(n, 1e-12f);
    x = __fdiv_rn(x,n); y = __fdiv_rn(y,n); z = __fdiv_rn(z,n);
}
__device__ __forceinline__ void cross3_(float ax,float ay,float az,
                                        float bx,float by,float bz,
                                        float &cx,float &cy,float &cz){
    cx = fsub_(fmul_(ay,bz), fmul_(az,by));
    cy = fsub_(fmul_(az,bx), fmul_(ax,bz));
    cz = fsub_(fmul_(ax,by), fmul_(ay,bx));
}
__device__ __forceinline__ float d2_exact(float xi,float yi,float zi,
                                          float xj,float yj,float zj){
    float dx = fsub_(xj,xi), dy = fsub_(yj,yi), dz = fsub_(zj,zi);
    return fadd_(fadd_(fmul_(dx,dx), fmul_(dy,dy)), fmul_(dz,dz));
}

// ---- FP32 Cody-Waite 2pi reduction ----
#define INV_2PI  0.15915494309189535f
#define PI2_C1   6.2831855f
#define PI2_C2  -1.7484555e-07f
#define PI2_C3  -5.4469782e-15f
__device__ __forceinline__ float red2pi_(float ang){
    float k = rintf(ang * INV_2PI);
    float r = fmaf(-k, PI2_C1, ang);
    r = fmaf(-k, PI2_C2, r);
    r = fmaf(-k, PI2_C3, r);
    return r;
}

// ---- per-node orientation matrix + AD ----
__device__ void node_work(const float* __restrict__ X, float* __restrict__ outAD,
                          int id, float* __restrict__ sOmRow){
    int b = id / NN, n = id % NN;

    float O0=0,O1=0,O2=0,O3v=0,O4=0,O5=0,O6=0,O7=0,O8=0;
    float a0=0,a1=0,a2=0;

    if (n >= 1 && n <= NN-3){
        const float* Xb = X + b*NN*3;
        float p0x=Xb[(n-1)*3+0], p0y=Xb[(n-1)*3+1], p0z=Xb[(n-1)*3+2];
        float p1x=Xb[(n  )*3+0], p1y=Xb[(n  )*3+1], p1z=Xb[(n  )*3+2];
        float p2x=Xb[(n+1)*3+0], p2y=Xb[(n+1)*3+1], p2z=Xb[(n+1)*3+2];
        float p3x=Xb[(n+2)*3+0], p3y=Xb[(n+2)*3+1], p3z=Xb[(n+2)*3+2];

        float u2x=fsub_(p1x,p0x), u2y=fsub_(p1y,p0y), u2z=fsub_(p1z,p0z); norm3_(u2x,u2y,u2z);
        float u1x=fsub_(p2x,p1x), u1y=fsub_(p2y,p1y), u1z=fsub_(p2z,p1z); norm3_(u1x,u1y,u1z);
        float u0x=fsub_(p3x,p2x), u0y=fsub_(p3y,p2y), u0z=fsub_(p3z,p2z); norm3_(u0x,u0y,u0z);

        float n2x,n2y,n2z; cross3_(u2x,u2y,u2z,u1x,u1y,u1z,n2x,n2y,n2z); norm3_(n2x,n2y,n2z);
        float n1x,n1y,n1z; cross3_(u1x,u1y,u1z,u0x,u0y,u0z,n1x,n1y,n1z); norm3_(n1x,n1y,n1z);

        const float lo = (float)(-1.0 + 1e-6);
        const float hi = (float)( 1.0 - 1e-6);
        float cosA = fminf(fmaxf(-dot3_(u1x,u1y,u1z,u0x,u0y,u0z), lo), hi);
        float A = acosf(cosA);
        float cosD = fminf(fmaxf(dot3_(n2x,n2y,n2z,n1x,n1y,n1z), lo), hi);
        float s = dot3_(u2x,u2y,u2z,n1x,n1y,n1z);
        float sg = (s > 0.0f) ? 1.0f : ((s < 0.0f) ? -1.0f : 0.0f);
        float Dang = fmul_(sg, acosf(cosD));

        float sA = sinf(A);
        a0 = cosf(A);
        a1 = fmul_(sA, cosf(Dang));
        a2 = fmul_(sA, sinf(Dang));

        float o1x=fsub_(u2x,u1x), o1y=fsub_(u2y,u1y), o1z=fsub_(u2z,u1z); norm3_(o1x,o1y,o1z);
        float cx,cy,cz; cross3_(o1x,o1y,o1z,n2x,n2y,n2z,cx,cy,cz);
        O0=o1x; O1=o1y; O2=o1z; O3v=n2x; O4=n2y; O5=n2z; O6=cx; O7=cy; O8=cz;
    }
    sOmRow[0]=O0; sOmRow[1]=O1; sOmRow[2]=O2; sOmRow[3]=O3v; sOmRow[4]=O4;
    sOmRow[5]=O5; sOmRow[6]=O6; sOmRow[7]=O7; sOmRow[8]=O8;
    outAD[id*3+0]=a0; outAD[id*3+1]=a1; outAD[id*3+2]=a2;
}

// ============================================================================
// Fused kernel v9: exact top-30 kNN + node + edge features, block = 8 rows.
// Pass 1: FMA-heavy binning (float clamp + IMAD nibble pack).
// Pass 2: fast-d2 recompute vs sliver threshold.
// Extraction: split-rank on exact (D, j) keys (pivot = bin-T lower edge).
// ============================================================================
#define TPB 256
#define RB  8
#define CAP 224

__global__ __launch_bounds__(TPB) void fused_kernel(
    const float* __restrict__ X, float* __restrict__ out)
{
    __shared__ __align__(16) unsigned int nib[NN];   // 16KB; reused by split-rank
    __shared__ unsigned long long cand[RB][CAP];     // 14KB
    __shared__ float stD[RB][KK];
    __shared__ int   stI[RB][KK];
    __shared__ float sOm[RB][9];
    __shared__ float sThr[RB];
    __shared__ int   sTbin[RB];
    __shared__ float sfreq[8];
    __shared__ float smu[15];
    __shared__ int   scnt[RB];

    float* outP  = out + OFF_POS;
    float* outAD = out + OFF_AD;
    float* outO  = out + OFF_OF;
    float* outG  = out + OFF_GS;
    float* outD  = out + OFF_DN;
    float* outE  = out + OFF_EI;

    const int t = threadIdx.x, w = t >> 5, lane = t & 31;
    const int blk = blockIdx.x;
    const int b   = blk / (NN/RB);
    const int r0  = (blk % (NN/RB))*RB;
    const float* Xb = X + b*NN*3;

    if (t < RB){
        node_work(X, outAD, b*NN + r0 + t, sOm[t]);
        scnt[t] = 0;
    }
    if (t >= 32 && t < 64){
        int u = t - 32;
        if (u < 8){
            float argf = __fmul_rn((float)(2*u), -0.5756462732485115f);
            sfreq[u] = (float)exp((double)argf);
        }
        if (u < 15) smu[u] = (float)((double)u * (20.0/14.0));
    }

    // row coords + row norms (expanded form)
    float xr[RB], yr[RB], zr[RB], nr[RB];
    #pragma unroll
    for (int r = 0; r < RB; r++){
        xr[r] = Xb[(r0+r)*3+0];
        yr[r] = Xb[(r0+r)*3+1];
        zr[r] = Xb[(r0+r)*3+2];
        nr[r] = fmaf(zr[r],zr[r], fmaf(yr[r],yr[r], xr[r]*xr[r]));
    }
    __syncthreads();

    // ---- pass 1: fast-d2 bin per (row, point); IMAD nibble pack ----
    // bin = exponent(clamp(d2, 1, 65535)) - 127  in [0,15]
    #pragma unroll 2
    for (int m = 0; m < NN/TPB; m++){
        int j = m*TPB + t;
        float xj = __ldg(&Xb[j*3+0]);
        float yj = __ldg(&Xb[j*3+1]);
        float zj = __ldg(&Xb[j*3+2]);
        float nj = fmaf(zj,zj, fmaf(yj,yj, xj*xj));
        unsigned int lo = 0u, hi = 0u;
        #pragma unroll
        for (int q = 3; q >= 0; q--){
            {
                const int r = q;
                float s  = fmaf(zr[r],zj, fmaf(yr[r],yj, xr[r]*xj));
                float d2 = fmaf(-2.0f, s, nr[r] + nj);
                float dc = fminf(fmaxf(d2, 1.0f), 65535.0f);
                lo = lo*16u + ((__float_as_uint(dc) >> 23) - 127u);
            }
            {
                const int r = q + 4;
                float s  = fmaf(zr[r],zj, fmaf(yr[r],yj, xr[r]*xj));
                float d2 = fmaf(-2.0f, s, nr[r] + nj);
                float dc = fminf(fmaxf(d2, 1.0f), 65535.0f);
                hi = hi*16u + ((__float_as_uint(dc) >> 23) - 127u);
            }
        }
        nib[j] = hi*65536u + lo;
    }
    __syncthreads();

    // ---- pass 1.5: warp w histograms row w from nibble cache (uint4) ----
    {
        unsigned int h0=0u, h1=0u, h2=0u, h3=0u;   // 16 bins x u8
        const int sh = w*4;
        const uint4* nib4 = (const uint4*)nib;
        #pragma unroll 2
        for (int u = 0; u < 32; u++){
            uint4 qv = nib4[u*32 + lane];
            unsigned int ws[4] = {qv.x, qv.y, qv.z, qv.w};
            #pragma unroll
            for (int e = 0; e < 4; e++){
                unsigned int bin = (ws[e] >> sh) & 15u;
                unsigned int add = 1u << ((bin & 3u) << 3);
                unsigned int sel = bin >> 2;
                if      (sel == 0u) h0 += add;
                else if (sel == 1u) h1 += add;
                else if (sel == 2u) h2 += add;
                else                h3 += add;
            }
        }
        unsigned int v[8];
        v[0]= h0      & 0x00FF00FFu; v[1]=(h0>>8) & 0x00FF00FFu;
        v[2]= h1      & 0x00FF00FFu; v[3]=(h1>>8) & 0x00FF00FFu;
        v[4]= h2      & 0x00FF00FFu; v[5]=(h2>>8) & 0x00FF00FFu;
        v[6]= h3      & 0x00FF00FFu; v[7]=(h3>>8) & 0x00FF00FFu;
        #pragma unroll
        for (int off = 16; off; off >>= 1){
            #pragma unroll
            for (int q = 0; q < 8; q++)
                v[q] += __shfl_xor_sync(0xffffffffu, v[q], off);
        }
        int cum = 0, T = 15;
        #pragma unroll
        for (int i = 0; i < 16; i++){
            unsigned int word = v[(i>>2)*2 + (i&1)];
            cum += (int)((word >> (((i>>1)&1)*16)) & 0xFFFFu);
            if (cum >= KK){ T = i; break; }
        }
        if (lane == 0){
            sTbin[w] = T;
            // bin <= T  <=>  d2c < 2^(T+1); sliver 1/64 covers fast-vs-exact eps
            sThr[w] = __uint_as_float(((unsigned int)(128 + T) << 23) | 0x020000u);
        }
    }
    __syncthreads();

    float Tl[RB];
    #pragma unroll
    for (int r = 0; r < RB; r++) Tl[r] = sThr[r];

    // ---- pass 2: recompute fast-d2, keep below sliver threshold ----
    #pragma unroll 2
    for (int m = 0; m < NN/TPB; m++){
        int j = m*TPB + t;
        float xj = __ldg(&Xb[j*3+0]);
        float yj = __ldg(&Xb[j*3+1]);
        float zj = __ldg(&Xb[j*3+2]);
        float nj = fmaf(zj,zj, fmaf(yj,yj, xj*xj));
        #pragma unroll
        for (int r = 0; r < RB; r++){
            float s  = fmaf(zr[r],zj, fmaf(yr[r],yj, xr[r]*xj));
            float d2 = fmaf(-2.0f, s, nr[r] + nj);
            if (d2 < Tl[r]){
                int pos = atomicAdd(&scnt[r], 1);
                if (pos < CAP) cand[r][pos] = (unsigned long long)j;
            }
        }
    }
    __syncthreads();

    // ---- extraction: exact (D, j) keys + split-rank (warp w = row w) ----
    {
        const int row = r0 + w;
        const int c = min(scnt[w], CAP);
        const int base = (b*NN + row)*KK;
        const float xi = xr[w], yi = yr[w], zi = zr[w];

        for (int idx = lane; idx < c; idx += 32){
            unsigned int j = (unsigned int)cand[w][idx];
            float xj = __ldg(&Xb[j*3+0]);
            float yj = __ldg(&Xb[j*3+1]);
            float zj = __ldg(&Xb[j*3+2]);
            float d2 = d2_exact(xi,yi,zi,xj,yj,zj);
            float D  = __fsqrt_rn(fadd_(d2, 1e-6f));
            cand[w][idx] = ((unsigned long long)__float_as_uint(D) << 32) | j;
        }
        __syncwarp();

        // pivot = lower edge of bin T mapped through the exact D transform
        const int T = sTbin[w];
        float pD = __fsqrt_rn(fadd_(__uint_as_float((unsigned int)(127 + T) << 23), 1e-6f));
        const unsigned long long Kp = ((unsigned long long)__float_as_uint(pD)) << 32;
        unsigned long long* sp = ((unsigned long long*)nib) + w*CAP;

        const int iters = (c + 31) >> 5;
        int totA = 0;
        for (int u = 0; u < iters; u++){
            int idx = u*32 + lane;
            bool A = (idx < c) && (cand[w][idx] < Kp);
            totA += __popc(__ballot_sync(0xffffffffu, A));
        }
        int runA = 0, runB = 0;
        for (int u = 0; u < iters; u++){
            int idx = u*32 + lane;
            bool valid = idx < c;
            unsigned long long k = valid ? cand[w][idx] : 0xFFFFFFFFFFFFFFFFull;
            bool A = valid && (k < Kp);
            unsigned int mA = __ballot_sync(0xffffffffu, A);
            unsigned int mB = __ballot_sync(0xffffffffu, valid && !A);
            if (valid){
                unsigned int below = (1u << lane) - 1u;
                int pos = A ? (runA + __popc(mA & below))
                            : (totA + runB + __popc(mB & below));
                sp[pos] = k;
            }
            runA += __popc(mA);
            runB += __popc(mB);
        }
        __syncwarp();

        for (int idx = lane; idx < c; idx += 32){
            unsigned long long k = sp[idx];
            bool isA = idx < totA;
            int s0 = isA ? 0 : totA;
            int s1 = isA ? totA : c;
            int rank = isA ? 0 : totA;
            for (int cc = s0; cc < s1; cc++)
                rank += (sp[cc] < k) ? 1 : 0;
            if (rank < KK){
                unsigned int jj = (unsigned int)(k & 0xFFFFFFFFull);
                float D = __uint_as_float((unsigned int)(k >> 32));
                outD[base + rank] = D;
                outE[base + rank] = (float)jj;
                stD[w][rank] = D;
                stI[w][rank] = (int)jj;
            }
        }
    }
    __syncthreads();

    // ---- edge phase A: positional encodings (8 x 30 x 16, coalesced) ----
    for (int id = t; id < RB*KK*16; id += TPB){
        int r = id / (KK*16);
        int q = id - r*(KK*16);
        int k = q >> 4, m = q & 15;
        int i = r0 + r;
        int j = stI[r][k];
        float d = fsub_((float)j, (float)i);
        float ang = fmul_(d, sfreq[m & 7]);
        float rr = red2pi_(ang);
        outP[(size_t)(b*NN + i)*(KK*16) + q] = (m < 8) ? __cosf(rr) : __sinf(rr);
    }

    // ---- edge phase B: gaussian smearing (8 x 30 x 15, coalesced) ----
    for (int id = t; id < RB*KK*15; id += TPB){
        int r = id / (KK*15);
        int q = id - r*(KK*15);
        int k = q / 15, m = q - k*15;
        float D  = stD[r][k];
        float tt = fsub_(D, smu[m]) * 0.74999998f;
        outG[(size_t)(b*NN + r0 + r)*(KK*15) + q] = __expf(-tt*tt);
    }

    // ---- edge phase C: dU via rsqrt normalize (8 x 30 edges) ----
    if (t < RB*KK){
        int r = t / KK, k = t - r*KK;
        int i = r0 + r;
        int j = stI[r][k];
        float dx = fsub_(Xb[j*3+0], Xb[i*3+0]);
        float dy = fsub_(Xb[j*3+1], Xb[i*3+1]);
        float dz = fsub_(Xb[j*3+2], Xb[i*3+2]);
        const float* Om = sOm[r];
        float v0 = dot3_(Om[0],Om[1],Om[2], dx,dy,dz);
        float v1 = dot3_(Om[3],Om[4],Om[5], dx,dy,dz);
        float v2 = dot3_(Om[6],Om[7],Om[8], dx,dy,dz);
        float s  = dot3_(v0,v1,v2,v0,v1,v2);
        float rn = rsqrtf(fmaxf(s, 1e-24f));
        size_t o = (size_t)((b*NN + i)*KK + k)*3;
        outO[o+0] = v0*rn;
        outO[o+1] = v1*rn;
        outO[o+2] = v2*rn;
    }
}

// ============================================================================
extern "C" void kernel_launch(void* const* d_in, const int* in_sizes, int n_in,
                              void* d_out, int out_size)
{
    const float* X = (const float*)d_in[0];
    float* out = (float*)d_out;
    fused_kernel<<<BB*NN/RB, TPB>>>(X, out);
}

// round 11
// speedup vs baseline: 1.6029x; 1.0245x over previous
#include <cuda_runtime.h>
#include <math.h>

#define BB 2
#define NN 4096
#define KK 30

#define SZ_POS (BB*NN*KK*16)
#define SZ_AD  (BB*NN*3)
#define SZ_OF  (BB*NN*KK*3)
#define SZ_GS  (BB*NN*KK*15)
#define SZ_DN  (BB*NN*KK)

#define OFF_POS 0
#define OFF_AD  (OFF_POS + SZ_POS)
#define OFF_OF  (OFF_AD  + SZ_AD)
#define OFF_GS  (OFF_OF  + SZ_OF)
#define OFF_DN  (OFF_GS  + SZ_GS)
#define OFF_EI  (OFF_DN  + SZ_DN)

typedef unsigned long long u64;
typedef unsigned int       u32;

// ---- scratch ----
static __device__ float4 g_pts4[BB*NN];   // (x, y, z, |p|^2)

// ---- packed f32x2 helpers (sm_103a FFMA2 path, PTX-only) ----
__device__ __forceinline__ u64 pack2(float lo, float hi){
    u64 d; asm("mov.b64 %0, {%1, %2};" : "=l"(d) : "f"(lo), "f"(hi)); return d;
}
__device__ __forceinline__ u64 fma2(u64 a, u64 b, u64 c){
    u64 d; asm("fma.rn.f32x2 %0, %1, %2, %3;" : "=l"(d) : "l"(a), "l"(b), "l"(c)); return d;
}
__device__ __forceinline__ u64 mul2(u64 a, u64 b){
    u64 d; asm("mul.rn.f32x2 %0, %1, %2;" : "=l"(d) : "l"(a), "l"(b)); return d;
}
__device__ __forceinline__ u64 add2(u64 a, u64 b){
    u64 d; asm("add.rn.f32x2 %0, %1, %2;" : "=l"(d) : "l"(a), "l"(b)); return d;
}

// ---- exact-rounding helpers (OUTPUT values / selection keys) ----
__device__ __forceinline__ float fadd_(float a, float b){ return __fadd_rn(a,b); }
__device__ __forceinline__ float fsub_(float a, float b){ return __fsub_rn(a,b); }
__device__ __forceinline__ float fmul_(float a, float b){ return __fmul_rn(a,b); }
__device__ __forceinline__ float dot3_(float ax,float ay,float az,
                                       float bx,float by,float bz){
    return fadd_(fadd_(fmul_(ax,bx), fmul_(ay,by)), fmul_(az,bz));
}
__device__ __forceinline__ void norm3_(float &x, float &y, float &z){
    float n = __fsqrt_rn(dot3_(x,y,z,x,y,z));
    n = fmaxf(n, 1e-12f);
    x = __fdiv_rn(x,n); y = __fdiv_rn(y,n); z = __fdiv_rn(z,n);
}
__device__ __forceinline__ void cross3_(float ax,float ay,float az,
                                        float bx,float by,float bz,
                                        float &cx,float &cy,float &cz){
    cx = fsub_(fmul_(ay,bz), fmul_(az,by));
    cy = fsub_(fmul_(az,bx), fmul_(ax,bz));
    cz = fsub_(fmul_(ax,by), fmul_(ay,bx));
}
__device__ __forceinline__ float d2_exact(float xi,float yi,float zi,
                                          float xj,float yj,float zj){
    float dx = fsub_(xj,xi), dy = fsub_(yj,yi), dz = fsub_(zj,zi);
    return fadd_(fadd_(fmul_(dx,dx), fmul_(dy,dy)), fmul_(dz,dz));
}

// ---- FP32 Cody-Waite 2pi reduction ----
#define INV_2PI  0.15915494309189535f
#define PI2_C1   6.2831855f
#define PI2_C2  -1.7484555e-07f
#define PI2_C3  -5.4469782e-15f
__device__ __forceinline__ float red2pi_(float ang){
    float k = rintf(ang * INV_2PI);
    float r = fmaf(-k, PI2_C1, ang);
    r = fmaf(-k, PI2_C2, r);
    r = fmaf(-k, PI2_C3, r);
    return r;
}

// ---- per-node orientation matrix + AD ----
__device__ void node_work(const float* __restrict__ X, float* __restrict__ outAD,
                          int id, float* __restrict__ sOmRow){
    int b = id / NN, n = id % NN;

    float O0=0,O1=0,O2=0,O3v=0,O4=0,O5=0,O6=0,O7=0,O8=0;
    float a0=0,a1=0,a2=0;

    if (n >= 1 && n <= NN-3){
        const float* Xb = X + b*NN*3;
        float p0x=Xb[(n-1)*3+0], p0y=Xb[(n-1)*3+1], p0z=Xb[(n-1)*3+2];
        float p1x=Xb[(n  )*3+0], p1y=Xb[(n  )*3+1], p1z=Xb[(n  )*3+2];
        float p2x=Xb[(n+1)*3+0], p2y=Xb[(n+1)*3+1], p2z=Xb[(n+1)*3+2];
        float p3x=Xb[(n+2)*3+0], p3y=Xb[(n+2)*3+1], p3z=Xb[(n+2)*3+2];

        float u2x=fsub_(p1x,p0x), u2y=fsub_(p1y,p0y), u2z=fsub_(p1z,p0z); norm3_(u2x,u2y,u2z);
        float u1x=fsub_(p2x,p1x), u1y=fsub_(p2y,p1y), u1z=fsub_(p2z,p1z); norm3_(u1x,u1y,u1z);
        float u0x=fsub_(p3x,p2x), u0y=fsub_(p3y,p2y), u0z=fsub_(p3z,p2z); norm3_(u0x,u0y,u0z);

        float n2x,n2y,n2z; cross3_(u2x,u2y,u2z,u1x,u1y,u1z,n2x,n2y,n2z); norm3_(n2x,n2y,n2z);
        float n1x,n1y,n1z; cross3_(u1x,u1y,u1z,u0x,u0y,u0z,n1x,n1y,n1z); norm3_(n1x,n1y,n1z);

        const float lo = (float)(-1.0 + 1e-6);
        const float hi = (float)( 1.0 - 1e-6);
        float cosA = fminf(fmaxf(-dot3_(u1x,u1y,u1z,u0x,u0y,u0z), lo), hi);
        float A = acosf(cosA);
        float cosD = fminf(fmaxf(dot3_(n2x,n2y,n2z,n1x,n1y,n1z), lo), hi);
        float s = dot3_(u2x,u2y,u2z,n1x,n1y,n1z);
        float sg = (s > 0.0f) ? 1.0f : ((s < 0.0f) ? -1.0f : 0.0f);
        float Dang = fmul_(sg, acosf(cosD));

        float sA = sinf(A);
        a0 = cosf(A);
        a1 = fmul_(sA, cosf(Dang));
        a2 = fmul_(sA, sinf(Dang));

        float o1x=fsub_(u2x,u1x), o1y=fsub_(u2y,u1y), o1z=fsub_(u2z,u1z); norm3_(o1x,o1y,o1z);
        float cx,cy,cz; cross3_(o1x,o1y,o1z,n2x,n2y,n2z,cx,cy,cz);
        O0=o1x; O1=o1y; O2=o1z; O3v=n2x; O4=n2y; O5=n2z; O6=cx; O7=cy; O8=cz;
    }
    sOmRow[0]=O0; sOmRow[1]=O1; sOmRow[2]=O2; sOmRow[3]=O3v; sOmRow[4]=O4;
    sOmRow[5]=O5; sOmRow[6]=O6; sOmRow[7]=O7; sOmRow[8]=O8;
    outAD[id*3+0]=a0; outAD[id*3+1]=a1; outAD[id*3+2]=a2;
}

// ---- pre-pass: pack coords + squared norms ----
__global__ void pack_kernel(const float* __restrict__ X){
    int id = blockIdx.x*blockDim.x + threadIdx.x;
    if (id < BB*NN){
        float x = X[id*3+0], y = X[id*3+1], z = X[id*3+2];
        g_pts4[id] = make_float4(x, y, z, fmaf(z,z, fmaf(y,y, x*x)));
    }
}

// ============================================================================
// Fused kernel v10: exact top-30 kNN + node + edge features, block = 8 rows.
// Packed f32x2 distance math; bias binning (no clamps); sign-mask pass 2;
// split-rank extraction on exact (D, j) keys.
// ============================================================================
#define TPB 256
#define RB  8
#define CAP 224

__global__ __launch_bounds__(TPB) void fused_kernel(
    const float* __restrict__ X, float* __restrict__ out)
{
    __shared__ __align__(16) u32 nib[NN];         // 16KB; reused by split-rank
    __shared__ u64   cand[RB][CAP];               // 14KB
    __shared__ float stD[RB][KK];
    __shared__ int   stI[RB][KK];
    __shared__ float sOm[RB][9];
    __shared__ float sThr[RB];
    __shared__ int   sTbin[RB];
    __shared__ float sfreq[8];
    __shared__ float smu[15];
    __shared__ int   scnt[RB];

    float* outP  = out + OFF_POS;
    float* outAD = out + OFF_AD;
    float* outO  = out + OFF_OF;
    float* outG  = out + OFF_GS;
    float* outD  = out + OFF_DN;
    float* outE  = out + OFF_EI;

    const int t = threadIdx.x, w = t >> 5, lane = t & 31;
    const int blk = blockIdx.x;
    const int b   = blk / (NN/RB);
    const int r0  = (blk % (NN/RB))*RB;
    const int bNN = b*NN;
    const float* Xb = X + b*NN*3;

    if (t < RB){
        node_work(X, outAD, bNN + r0 + t, sOm[t]);
        scnt[t] = 0;
    }
    if (t >= 32 && t < 64){
        int u = t - 32;
        if (u < 8){
            float argf = __fmul_rn((float)(2*u), -0.5756462732485115f);
            sfreq[u] = (float)exp((double)argf);
        }
        if (u < 15) smu[u] = (float)((double)u * (20.0/14.0));
    }

    // packed row registers: pair (q, q+4); nr biased by +1.01 (bin bias)
    u64 xr2[4], yr2[4], zr2[4], nr2[4];
    #pragma unroll
    for (int q = 0; q < 4; q++){
        float4 pa = g_pts4[bNN + r0 + q];
        float4 pb = g_pts4[bNN + r0 + q + 4];
        xr2[q] = pack2(pa.x, pb.x);
        yr2[q] = pack2(pa.y, pb.y);
        zr2[q] = pack2(pa.z, pb.z);
        nr2[q] = pack2(pa.w + 1.01f, pb.w + 1.01f);
    }
    const u64 M2 = pack2(-2.0f, -2.0f);
    __syncthreads();

    // ---- pass 1: packed fast-d2' bins, nibble cache ----
    // d2' = |i-j|^2 + 1.01 (approx) >= 1.007 -> bin = exponent - 127 in [0,15]
    #pragma unroll 2
    for (int m = 0; m < NN/TPB; m++){
        int j = m*TPB + t;
        float4 p = g_pts4[bNN + j];
        u64 xjj = pack2(p.x, p.x);
        u64 yjj = pack2(p.y, p.y);
        u64 zjj = pack2(p.z, p.z);
        u64 njj = pack2(p.w, p.w);
        u32 nibLo = 0u, nibHi = 0u;
        #pragma unroll
        for (int q = 3; q >= 0; q--){
            u64 s2 = fma2(xr2[q], xjj, fma2(yr2[q], yjj, mul2(zr2[q], zjj)));
            u64 d2 = fma2(M2, s2, add2(nr2[q], njj));
            u32 lo32 = (u32)d2;
            u32 hi32 = (u32)(d2 >> 32);
            nibLo = nibLo*16u + ((lo32 - 0x3F800000u) >> 23);
            nibHi = nibHi*16u + ((hi32 - 0x3F800000u) >> 23);
        }
        nib[j] = nibHi*65536u + nibLo;
    }
    __syncthreads();

    // ---- pass 1.5: warp w histograms row w from nibble cache (uint4) ----
    {
        u32 h0=0u, h1=0u, h2=0u, h3=0u;   // 16 bins x u8
        const int sh = w*4;
        const uint4* nib4 = (const uint4*)nib;
        #pragma unroll 2
        for (int u = 0; u < 32; u++){
            uint4 qv = nib4[u*32 + lane];
            u32 ws[4] = {qv.x, qv.y, qv.z, qv.w};
            #pragma unroll
            for (int e = 0; e < 4; e++){
                u32 bin = (ws[e] >> sh) & 15u;
                u32 add = 1u << ((bin & 3u) << 3);
                u32 sel = bin >> 2;
                if      (sel == 0u) h0 += add;
                else if (sel == 1u) h1 += add;
                else if (sel == 2u) h2 += add;
                else                h3 += add;
            }
        }
        u32 v[8];
        v[0]= h0      & 0x00FF00FFu; v[1]=(h0>>8) & 0x00FF00FFu;
        v[2]= h1      & 0x00FF00FFu; v[3]=(h1>>8) & 0x00FF00FFu;
        v[4]= h2      & 0x00FF00FFu; v[5]=(h2>>8) & 0x00FF00FFu;
        v[6]= h3      & 0x00FF00FFu; v[7]=(h3>>8) & 0x00FF00FFu;
        #pragma unroll
        for (int off = 16; off; off >>= 1){
            #pragma unroll
            for (int q = 0; q < 8; q++)
                v[q] += __shfl_xor_sync(0xffffffffu, v[q], off);
        }
        int cum = 0, T = 15;
        #pragma unroll
        for (int i = 0; i < 16; i++){
            u32 word = v[(i>>2)*2 + (i&1)];
            cum += (int)((word >> (((i>>1)&1)*16)) & 0xFFFFu);
            if (cum >= KK){ T = i; break; }
        }
        if (lane == 0){
            sTbin[w] = T;
            // keep: d2' < 2^(T+1) * (1 + 1/64); sliver covers fast-vs-exact eps
            sThr[w] = __uint_as_float(((u32)(128 + T) << 23) | 0x020000u);
        }
    }
    __syncthreads();

    // negated packed thresholds per row pair
    u64 nThr2[4];
    #pragma unroll
    for (int q = 0; q < 4; q++)
        nThr2[q] = pack2(-sThr[q], -sThr[q+4]);

    // ---- pass 2: packed recompute, sign-mask keep test ----
    #pragma unroll 2
    for (int m = 0; m < NN/TPB; m++){
        int j = m*TPB + t;
        float4 p = g_pts4[bNN + j];
        u64 xjj = pack2(p.x, p.x);
        u64 yjj = pack2(p.y, p.y);
        u64 zjj = pack2(p.z, p.z);
        u64 njj = pack2(p.w, p.w);
        #pragma unroll
        for (int q = 0; q < 4; q++){
            u64 s2 = fma2(xr2[q], xjj, fma2(yr2[q], yjj, mul2(zr2[q], zjj)));
            u64 d2 = fma2(M2, s2, add2(nr2[q], njj));
            u64 df = add2(d2, nThr2[q]);          // d2' - thr, per half
            if (df & 0x8000000080000000ull){
                if ((u32)(df >> 31) & 1u){        // low half negative -> row q
                    int pos = atomicAdd(&scnt[q], 1);
                    if (pos < CAP) cand[q][pos] = (u64)j;
                }
                if (df >> 63){                    // high half -> row q+4
                    int pos = atomicAdd(&scnt[q+4], 1);
                    if (pos < CAP) cand[q+4][pos] = (u64)j;
                }
            }
        }
    }
    __syncthreads();

    // ---- extraction: exact (D, j) keys + split-rank (warp w = row w) ----
    {
        const int row = r0 + w;
        const int c = min(scnt[w], CAP);
        const int base = (bNN + row)*KK;
        const float xi = Xb[row*3+0], yi = Xb[row*3+1], zi = Xb[row*3+2];

        for (int idx = lane; idx < c; idx += 32){
            u32 j = (u32)cand[w][idx];
            float xj = __ldg(&Xb[j*3+0]);
            float yj = __ldg(&Xb[j*3+1]);
            float zj = __ldg(&Xb[j*3+2]);
            float d2 = d2_exact(xi,yi,zi,xj,yj,zj);
            float D  = __fsqrt_rn(fadd_(d2, 1e-6f));
            cand[w][idx] = ((u64)__float_as_uint(D) << 32) | j;
        }
        __syncwarp();

        // pivot: lower edge of bin T mapped to exact-D domain (any pivot is valid)
        const int T = sTbin[w];
        float pd2 = fmaxf(__uint_as_float((u32)(127 + T) << 23) - 1.01f, 0.0f);
        float pD  = __fsqrt_rn(fadd_(pd2, 1e-6f));
        const u64 Kp = ((u64)__float_as_uint(pD)) << 32;
        u64* sp = ((u64*)nib) + w*CAP;

        const int iters = (c + 31) >> 5;
        int totA = 0;
        for (int u = 0; u < iters; u++){
            int idx = u*32 + lane;
            bool A = (idx < c) && (cand[w][idx] < Kp);
            totA += __popc(__ballot_sync(0xffffffffu, A));
        }
        int runA = 0, runB = 0;
        for (int u = 0; u < iters; u++){
            int idx = u*32 + lane;
            bool valid = idx < c;
            u64 k = valid ? cand[w][idx] : 0xFFFFFFFFFFFFFFFFull;
            bool A = valid && (k < Kp);
            u32 mA = __ballot_sync(0xffffffffu, A);
            u32 mB = __ballot_sync(0xffffffffu, valid && !A);
            if (valid){
                u32 below = (1u << lane) - 1u;
                int pos = A ? (runA + __popc(mA & below))
                            : (totA + runB + __popc(mB & below));
                sp[pos] = k;
            }
            runA += __popc(mA);
            runB += __popc(mB);
        }
        __syncwarp();

        for (int idx = lane; idx < c; idx += 32){
            u64 k = sp[idx];
            bool isA = idx < totA;
            int s0 = isA ? 0 : totA;
            int s1 = isA ? totA : c;
            int rank = isA ? 0 : totA;
            for (int cc = s0; cc < s1; cc++)
                rank += (sp[cc] < k) ? 1 : 0;
            if (rank < KK){
                u32 jj = (u32)(k & 0xFFFFFFFFull);
                float D = __uint_as_float((u32)(k >> 32));
                outD[base + rank] = D;
                outE[base + rank] = (float)jj;
                stD[w][rank] = D;
                stI[w][rank] = (int)jj;
            }
        }
    }
    __syncthreads();

    // ---- edge phase A: positional encodings (8 x 30 x 16, coalesced) ----
    for (int id = t; id < RB*KK*16; id += TPB){
        int r = id / (KK*16);
        int q = id - r*(KK*16);
        int k = q >> 4, m = q & 15;
        int i = r0 + r;
        int j = stI[r][k];
        float d = fsub_((float)j, (float)i);
        float ang = fmul_(d, sfreq[m & 7]);
        float rr = red2pi_(ang);
        outP[(size_t)(bNN + i)*(KK*16) + q] = (m < 8) ? __cosf(rr) : __sinf(rr);
    }

    // ---- edge phase B: gaussian smearing (8 x 30 x 15, coalesced) ----
    for (int id = t; id < RB*KK*15; id += TPB){
        int r = id / (KK*15);
        int q = id - r*(KK*15);
        int k = q / 15, m = q - k*15;
        float D  = stD[r][k];
        float tt = fsub_(D, smu[m]) * 0.74999998f;
        outG[(size_t)(bNN + r0 + r)*(KK*15) + q] = __expf(-tt*tt);
    }

    // ---- edge phase C: dU via rsqrt normalize (8 x 30 edges) ----
    if (t < RB*KK){
        int r = t / KK, k = t - r*KK;
        int i = r0 + r;
        int j = stI[r][k];
        float dx = fsub_(Xb[j*3+0], Xb[i*3+0]);
        float dy = fsub_(Xb[j*3+1], Xb[i*3+1]);
        float dz = fsub_(Xb[j*3+2], Xb[i*3+2]);
        const float* Om = sOm[r];
        float v0 = dot3_(Om[0],Om[1],Om[2], dx,dy,dz);
        float v1 = dot3_(Om[3],Om[4],Om[5], dx,dy,dz);
        float v2 = dot3_(Om[6],Om[7],Om[8], dx,dy,dz);
        float s  = dot3_(v0,v1,v2,v0,v1,v2);
        float rn = rsqrtf(fmaxf(s, 1e-24f));
        size_t o = (size_t)((bNN + i)*KK + k)*3;
        outO[o+0] = v0*rn;
        outO[o+1] = v1*rn;
        outO[o+2] = v2*rn;
    }
}

// ============================================================================
extern "C" void kernel_launch(void* const* d_in, const int* in_sizes, int n_in,
                              void* d_out, int out_size)
{
    const float* X = (const float*)d_in[0];
    float* out = (float*)d_out;
    pack_kernel<<<(BB*NN + 255)/256, 256>>>(X);
    fused_kernel<<<BB*NN/RB, TPB>>>(X, out);
}